// round 3
// baseline (speedup 1.0000x reference)
#include <cuda_runtime.h>

// Problem constants (fixed by the reference)
#define HH   352
#define WW   1216
#define BB   2
#define PP   65536
#define CC   64
#define KTOP 8
#define SLOTS 16
#define HWPIX (HH*WW)          // 428032
#define NPIX  (BB*HWPIX)       // 856064

// r = RADIUS_PX / max(H,W) * 2 = 3/1216 (double, rounded to f32 at use like jax)
#define RR_F   ((float)((3.0/1216.0)*(3.0/1216.0)))   // r*r; also dist divisor (RAD_POW=2)
#define INVW2  ((float)(2.0/1216.0))
#define INVH2  ((float)(2.0/352.0))

// ---- scratch (allocation-free: __device__ globals) ----
__device__ int                g_cnt[NPIX];
__device__ unsigned long long g_key[NPIX * SLOTS];     // (z_bits<<32) | pid
__device__ float              g_d2 [NPIX * SLOTS];
__device__ float              g_feats[BB * PP * CC];   // transposed features [B*P, C]

// ---------------------------------------------------------------------------
__global__ void zero_cnt_kernel() {
    int i = blockIdx.x * blockDim.x + threadIdx.x;
    if (i < NPIX) g_cnt[i] = 0;
}

// ---------------------------------------------------------------------------
// src [B, C, P] -> feats [B*P, C]  (32x32 smem tile transpose)
__global__ void transpose_kernel(const float* __restrict__ src) {
    __shared__ float tile[32][33];
    int b  = blockIdx.z;
    int ct = blockIdx.y;           // which 32-channel half (C=64 -> 2)
    int pt = blockIdx.x;           // which 32-point tile (P/32 = 2048)
    int tx = threadIdx.x, ty = threadIdx.y;

    const float* s = src + ((size_t)b * CC + ct * 32) * PP + (size_t)pt * 32;
    #pragma unroll
    for (int i = 0; i < 32; i += 8)
        tile[ty + i][tx] = s[(size_t)(ty + i) * PP + tx];
    __syncthreads();

    float* d = g_feats + ((size_t)b * PP + pt * 32) * CC + ct * 32;
    #pragma unroll
    for (int i = 0; i < 32; i += 8)
        d[(size_t)(ty + i) * CC + tx] = tile[tx][ty + i];
}

// ---------------------------------------------------------------------------
// One thread per packed point id (pid = b*P + p).
__global__ void scatter_kernel(const float* __restrict__ pts) {
    int pid = blockIdx.x * blockDim.x + threadIdx.x;
    if (pid >= BB * PP) return;

    float x = pts[pid * 3 + 0];
    float y = pts[pid * 3 + 1];
    float z = pts[pid * 3 + 2];
    if (!(z > 0.0f)) return;

    int b  = pid >> 16;  // P = 65536
    int i0 = (int)floorf((y + 1.0f) * 0.5f * (float)HH);
    int j0 = (int)floorf((x + 1.0f) * 0.5f * (float)WW);

    unsigned long long kk =
        ((unsigned long long)__float_as_uint(z) << 32) | (unsigned int)pid;

    #pragma unroll
    for (int di = -1; di <= 1; di++) {
        int ii = i0 + di;
        if (ii < 0 || ii >= HH) continue;
        float yc = ((float)ii + 0.5f) * INVH2 - 1.0f;
        float dy = y - yc;
        float dy2 = dy * dy;
        #pragma unroll
        for (int dj = -2; dj <= 2; dj++) {
            int jj = j0 + dj;
            if (jj < 0 || jj >= WW) continue;
            float xc = ((float)jj + 0.5f) * INVW2 - 1.0f;
            float dx = x - xc;
            float d2 = dx * dx + dy2;
            if (d2 < RR_F) {
                int pix = (b * HH + ii) * WW + jj;
                int s = atomicAdd(&g_cnt[pix], 1);
                if (s < SLOTS) {
                    g_key[pix * SLOTS + s] = kk;
                    g_d2 [pix * SLOTS + s] = d2;
                }
            }
        }
    }
}

// ---------------------------------------------------------------------------
// One thread per pixel. Sort candidates by (z, pid) (deterministic, matches
// reference lexsort), keep 8 nearest, composite all 64 channels in registers.
__global__ void __launch_bounds__(256) composite_kernel(float* __restrict__ out) {
    int pix = blockIdx.x * blockDim.x + threadIdx.x;
    if (pix >= NPIX) return;

    int b   = pix / HWPIX;
    int rem = pix - b * HWPIX;     // h*W + w

    int n = g_cnt[pix];
    if (n > SLOTS) n = SLOTS;

    unsigned long long key[SLOTS];
    float dd[SLOTS];
    int base = pix * SLOTS;
    for (int i = 0; i < n; i++) {
        unsigned long long k = g_key[base + i];
        float d = g_d2[base + i];
        int j = i;
        while (j > 0 && key[j - 1] > k) {
            key[j] = key[j - 1];
            dd[j]  = dd[j - 1];
            j--;
        }
        key[j] = k;
        dd[j]  = d;
    }
    int m = n < KTOP ? n : KTOP;

    float acc[CC];
    #pragma unroll
    for (int c = 0; c < CC; c++) acc[c] = 0.0f;

    const float4* f4 = (const float4*)g_feats;
    for (int k = 0; k < m; k++) {
        float dist = dd[k] / RR_F;
        dist = fminf(fmaxf(dist, 0.001f), 1.0f);
        float wk = 1.0f - sqrtf(dist);
        int p = (int)(unsigned int)(key[k] & 0xffffffffu);
        #pragma unroll
        for (int c4 = 0; c4 < CC / 4; c4++) {
            float4 f = f4[(size_t)p * (CC / 4) + c4];
            acc[4 * c4 + 0] += wk * f.x;
            acc[4 * c4 + 1] += wk * f.y;
            acc[4 * c4 + 2] += wk * f.z;
            acc[4 * c4 + 3] += wk * f.w;
        }
    }

    float* o = out + (size_t)b * CC * HWPIX + rem;
    #pragma unroll
    for (int c = 0; c < CC; c++)
        o[(size_t)c * HWPIX] = acc[c];
}

// ---------------------------------------------------------------------------
extern "C" void kernel_launch(void* const* d_in, const int* in_sizes, int n_in,
                              void* d_out, int out_size) {
    const float* pts = (const float*)d_in[0];  // [B, P, 3]
    const float* src = (const float*)d_in[1];  // [B, C, P]
    float* out = (float*)d_out;                // [B, C, H, W]

    zero_cnt_kernel<<<(NPIX + 255) / 256, 256>>>();
    scatter_kernel<<<(BB * PP + 127) / 128, 128>>>(pts);
    {
        dim3 grid(PP / 32, CC / 32, BB);
        dim3 block(32, 8);
        transpose_kernel<<<grid, block>>>(src);
    }
    composite_kernel<<<(NPIX + 255) / 256, 256>>>(out);
}